// round 5
// baseline (speedup 1.0000x reference)
#include <cuda_runtime.h>
#include <math.h>
#include <stdint.h>

// Problem constants
#define EMBED   256
#define NHEADS  4
#define HDIM    64
#define BATCHB  4
#define SEQ     2048
#define ROWS    (BATCHB*SEQ)          // 8192 rows per stream
#define BH      (BATCHB*NHEADS)       // 16 batched attention slices
#define SZ      ((long)ROWS*EMBED)    // 2M floats per [ROWS][EMBED] tensor

// rounded-weight scratch offsets (floats)
#define WQK_R   0
#define WV_R    65536
#define WOUT_R  131072
#define W0BOT_R 196608
#define W3_R    327680
#define WSCRATCH_TOTAL 458752

// ---------------- scratch (static device globals; no allocation) -----------
__device__ float g_xr [2*SZ];           // tf32-rounded x0, x1
__device__ float g_w  [WSCRATCH_TOTAL]; // tf32-rounded weights
__device__ float g_Bst[512*512];        // stacked FFN B: [W0top_r ; Wfused]
__device__ float g_bf [512];            // fused FFN bias
__device__ float g_qkv[4*SZ];           // qk0, qk1, v0, v1 (tf32)
__device__ float g_m  [2*SZ];           // attention outputs (tf32)
__device__ float g_y  [2L*ROWS*512];    // FFN hidden (tf32 after ln_gelu)

// ---------------- helpers ----------------------------------------------------
__device__ __forceinline__ float tf32r(float x) {
    uint32_t u;
    asm("cvt.rna.tf32.f32 %0, %1;" : "=r"(u) : "f"(x));
    return __uint_as_float(u);
}
__device__ __forceinline__ void mma_tf32(float d[4], const uint32_t a[4], const uint32_t b[2]) {
    asm volatile(
        "mma.sync.aligned.m16n8k8.row.col.f32.tf32.tf32.f32 "
        "{%0,%1,%2,%3},{%4,%5,%6,%7},{%8,%9},{%0,%1,%2,%3};"
        : "+f"(d[0]), "+f"(d[1]), "+f"(d[2]), "+f"(d[3])
        : "r"(a[0]), "r"(a[1]), "r"(a[2]), "r"(a[3]), "r"(b[0]), "r"(b[1]));
}
__device__ __forceinline__ void cpa16(void* smem, const void* gmem) {
    uint32_t s = (uint32_t)__cvta_generic_to_shared(smem);
    asm volatile("cp.async.cg.shared.global [%0], [%1], 16;" :: "r"(s), "l"(gmem));
}
__device__ __forceinline__ void cp_commit() { asm volatile("cp.async.commit_group;"); }
__device__ __forceinline__ void cp_wait2()  { asm volatile("cp.async.wait_group 2;"); }
__device__ __forceinline__ void cp_wait1()  { asm volatile("cp.async.wait_group 1;"); }
__device__ __forceinline__ void cp_wait0()  { asm volatile("cp.async.wait_group 0;"); }

// ---------------- tf32 multi round-copy --------------------------------------
#define NJOBS 8
struct CopyJobs {
    const float* src[NJOBS];
    float*       dst[NJOBS];
    long         n[NJOBS];     // multiples of 4
};
__global__ void tf32_copy_multi(CopyJobs j)
{
    const int jb = blockIdx.y;
    const float* s = j.src[jb];
    float* d = j.dst[jb];
    const long n4 = j.n[jb] >> 2;
    for (long i = blockIdx.x * blockDim.x + threadIdx.x; i < n4;
         i += (long)gridDim.x * blockDim.x) {
        float4 v = *(const float4*)(s + i * 4);
        v.x = tf32r(v.x); v.y = tf32r(v.y); v.z = tf32r(v.z); v.w = tf32r(v.w);
        *(float4*)(d + i * 4) = v;
    }
}

// ---------------- fused FFN bias: bf = b0 + bout @ W0bot ---------------------
__global__ void bias_fuse_kernel(const float* __restrict__ bout,
                                 const float* __restrict__ W0bot,  // [256][512]
                                 const float* __restrict__ b0,
                                 float* __restrict__ bf)
{
    int n = blockIdx.x * blockDim.x + threadIdx.x;   // 0..511
    float s = b0[n];
    for (int k = 0; k < 256; k++) s += bout[k] * W0bot[(long)k * 512 + n];
    bf[n] = s;
}

// ---------------- pipelined tensor-core tf32 GEMM ----------------------------
// Inputs MUST be tf32-rounded already. BM=BN=128, BK=16, 256 threads, 3 stages.
// z&1 selects A (A0/A1) and resid; z>>1 selects B/bias.
// KSPLIT: for k >= K/2, A switches to (A2 + (z&1)*a2Stride).
template<int KSPLIT, int EPI_TF32>
__global__ __launch_bounds__(256)
void mma_gemm(
    const float* __restrict__ A0, const float* __restrict__ A1,
    const float* __restrict__ A2, long a2Stride,
    const float* __restrict__ B0, const float* __restrict__ B1,
    const float* __restrict__ bias0, const float* __restrict__ bias1,
    const float* __restrict__ res0, const float* __restrict__ res1,
    float* __restrict__ Cb, long cStride,
    int M, int N, int K, int lda, int ldb, int ldc, int ldr)
{
    constexpr int ASTR = 20;
    constexpr int BSTR = 136;
    __shared__ float As[3][128][ASTR];
    __shared__ float Bs[3][16][BSTR];

    const int z = blockIdx.z;
    const float* Aa  = (z & 1) ? A1 : A0;
    const float* Ab  = KSPLIT ? (A2 + (z & 1) * a2Stride) : nullptr;
    const float* B   = (z >> 1) ? B1 : B0;
    const float* bias= (z >> 1) ? bias1 : bias0;
    const float* res = (z & 1) ? res1 : res0;
    float* C = Cb + (long)z * cStride;

    const int tid  = threadIdx.x;
    const int warp = tid >> 5;
    const int lane = tid & 31;
    const int qr = lane >> 2, qc = lane & 3;
    const int rowBase = blockIdx.y * 128;
    const int colBase = blockIdx.x * 128;
    const int wm0 = (warp >> 1) * 32;
    const int wn0 = (warp & 1) * 64;

    float acc[2][8][4];
    #pragma unroll
    for (int i = 0; i < 2; i++)
        #pragma unroll
        for (int j = 0; j < 8; j++)
            #pragma unroll
            for (int r = 0; r < 4; r++) acc[i][j][r] = 0.f;

    const int KT = K / 16;
    const int Khalf = K / 2;

    auto loadTile = [&](int st, int kt) {
        int k0 = kt * 16;
        const float* Ac; int kb;
        if (KSPLIT && k0 >= Khalf) { Ac = Ab; kb = k0 - Khalf; }
        else                       { Ac = Aa; kb = k0; }
        #pragma unroll
        for (int i = tid; i < 512; i += 256) {
            int m = i >> 2, kg = i & 3;
            cpa16(&As[st][m][kg * 4], Ac + (long)(rowBase + m) * lda + kb + kg * 4);
        }
        #pragma unroll
        for (int i = tid; i < 512; i += 256) {
            int r = i >> 5, c4 = (i & 31) * 4;
            cpa16(&Bs[st][r][c4], B + (long)(k0 + r) * ldb + colBase + c4);
        }
    };

    loadTile(0, 0); cp_commit();
    if (KT > 1) { loadTile(1, 1); cp_commit(); }

    for (int kt = 0; kt < KT; kt++) {
        int st = kt % 3;
        if (kt + 2 < KT) { loadTile((kt + 2) % 3, kt + 2); cp_commit(); cp_wait2(); }
        else if (kt + 1 < KT) { cp_wait1(); }
        else { cp_wait0(); }
        __syncthreads();

        #pragma unroll
        for (int ks = 0; ks < 16; ks += 8) {
            uint32_t af[2][4];
            #pragma unroll
            for (int mt = 0; mt < 2; mt++) {
                int mrr = wm0 + mt * 16;
                af[mt][0] = __float_as_uint(As[st][mrr + qr    ][ks + qc]);
                af[mt][1] = __float_as_uint(As[st][mrr + qr + 8][ks + qc]);
                af[mt][2] = __float_as_uint(As[st][mrr + qr    ][ks + qc + 4]);
                af[mt][3] = __float_as_uint(As[st][mrr + qr + 8][ks + qc + 4]);
            }
            uint32_t bf[8][2];
            #pragma unroll
            for (int nt = 0; nt < 8; nt++) {
                int nr = wn0 + nt * 8;
                bf[nt][0] = __float_as_uint(Bs[st][ks + qc    ][nr + qr]);
                bf[nt][1] = __float_as_uint(Bs[st][ks + qc + 4][nr + qr]);
            }
            #pragma unroll
            for (int mt = 0; mt < 2; mt++)
                #pragma unroll
                for (int nt = 0; nt < 8; nt++)
                    mma_tf32(acc[mt][nt], af[mt], bf[nt]);
        }
        __syncthreads();
    }

    #pragma unroll
    for (int mt = 0; mt < 2; mt++) {
        #pragma unroll
        for (int nt = 0; nt < 8; nt++) {
            int gm = rowBase + wm0 + mt * 16 + qr;
            int gn = colBase + wn0 + nt * 8 + qc * 2;
            float b0v = bias ? bias[gn] : 0.f;
            float b1v = bias ? bias[gn + 1] : 0.f;
            float v0 = acc[mt][nt][0] + b0v;
            float v1 = acc[mt][nt][1] + b1v;
            float v2 = acc[mt][nt][2] + b0v;
            float v3 = acc[mt][nt][3] + b1v;
            if (res) {
                const float2 r0 = *(const float2*)(res + (long)gm * ldr + gn);
                const float2 r1 = *(const float2*)(res + (long)(gm + 8) * ldr + gn);
                v0 += r0.x; v1 += r0.y; v2 += r1.x; v3 += r1.y;
            }
            if (EPI_TF32) {
                v0 = tf32r(v0); v1 = tf32r(v1); v2 = tf32r(v2); v3 = tf32r(v3);
            }
            *(float2*)(C + (long)gm * ldc + gn)       = make_float2(v0, v1);
            *(float2*)(C + (long)(gm + 8) * ldc + gn) = make_float2(v2, v3);
        }
    }
}

// ---------------- fused flash cross-attention (pipelined) --------------------
#define KSTR 68
#define VSTR 72
#define FL_P   0
#define FL_K0  4352
#define FL_V0  13056
#define FL_SMEM ((13056 + 2*4608) * 4)   // 89088 bytes

__global__ __launch_bounds__(128)
void flash_kernel(const float* __restrict__ qkv, float* __restrict__ mOut)
{
    extern __shared__ float sm[];
    const int z = blockIdx.z;
    const float* Qg = qkv + (long)z * SZ;
    const float* Kg = qkv + (long)(1 - z) * SZ;
    const float* Vg = qkv + (long)(3 - z) * SZ;
    float*       Og = mOut + (long)z * SZ;

    float (*Ps)[KSTR] = (float(*)[KSTR])(sm + FL_P);

    const long base = (long)(blockIdx.y >> 2) * SEQ * EMBED + (blockIdx.y & 3) * HDIM;
    const float* Qp = Qg + base + (long)blockIdx.x * 64 * EMBED;
    const float* K0 = Kg + base;
    const float* V0 = Vg + base;
    float*       Op = Og + base + (long)blockIdx.x * 64 * EMBED;

    const int tid  = threadIdx.x;
    const int warp = tid >> 5;
    const int lane = tid & 31;
    const int qr = lane >> 2, qc = lane & 3;
    const int mr = warp * 16;

    auto loadKV = [&](int st, int kb) {
        float* Ks = sm + FL_K0 + st * 4352;
        float* Vs = sm + FL_V0 + st * 4608;
        const float* Kp = K0 + (long)kb * 64 * EMBED;
        const float* Vp = V0 + (long)kb * 64 * EMBED;
        #pragma unroll
        for (int i = tid; i < 64 * 16; i += 128) {
            int r = i >> 4, c4 = (i & 15) * 4;
            cpa16(Ks + r * KSTR + c4, Kp + (long)r * EMBED + c4);
            cpa16(Vs + r * VSTR + c4, Vp + (long)r * EMBED + c4);
        }
    };

    loadKV(0, 0);
    cp_commit();

    #pragma unroll
    for (int i = tid; i < 64 * 16; i += 128) {
        int r = i >> 4, c4 = (i & 15) * 4;
        *(float4*)&Ps[r][c4] = *(const float4*)(Qp + (long)r * EMBED + c4);
    }
    __syncthreads();
    uint32_t qf[8][4];
    #pragma unroll
    for (int ks = 0; ks < 8; ks++) {
        qf[ks][0] = __float_as_uint(Ps[mr+qr  ][ks*8+qc  ]);
        qf[ks][1] = __float_as_uint(Ps[mr+qr+8][ks*8+qc  ]);
        qf[ks][2] = __float_as_uint(Ps[mr+qr  ][ks*8+qc+4]);
        qf[ks][3] = __float_as_uint(Ps[mr+qr+8][ks*8+qc+4]);
    }
    __syncthreads();

    float oacc[8][4];
    #pragma unroll
    for (int nt = 0; nt < 8; nt++)
        #pragma unroll
        for (int j = 0; j < 4; j++) oacc[nt][j] = 0.f;
    float mrow0 = -1e30f, mrow1 = -1e30f, lrow0 = 0.f, lrow1 = 0.f;

    for (int kb = 0; kb < SEQ / 64; kb++) {
        int st = kb & 1;
        if (kb + 1 < SEQ / 64) { loadKV(st ^ 1, kb + 1); cp_commit(); cp_wait1(); }
        else                   { cp_wait0(); }
        __syncthreads();

        const float* Ks = sm + FL_K0 + st * 4352;
        const float* Vs = sm + FL_V0 + st * 4608;

        float s[8][4];
        #pragma unroll
        for (int nt = 0; nt < 8; nt++)
            #pragma unroll
            for (int j = 0; j < 4; j++) s[nt][j] = 0.f;
        #pragma unroll
        for (int ks = 0; ks < 8; ks++) {
            #pragma unroll
            for (int nt = 0; nt < 8; nt++) {
                uint32_t bb[2] = {
                    __float_as_uint(Ks[(nt*8+qr)*KSTR + ks*8+qc    ]),
                    __float_as_uint(Ks[(nt*8+qr)*KSTR + ks*8+qc + 4]) };
                mma_tf32(s[nt], qf[ks], bb);
            }
        }

        float mx0 = -1e30f, mx1 = -1e30f;
        #pragma unroll
        for (int nt = 0; nt < 8; nt++) {
            s[nt][0] *= 0.125f; s[nt][1] *= 0.125f;
            s[nt][2] *= 0.125f; s[nt][3] *= 0.125f;
            mx0 = fmaxf(mx0, fmaxf(s[nt][0], s[nt][1]));
            mx1 = fmaxf(mx1, fmaxf(s[nt][2], s[nt][3]));
        }
        mx0 = fmaxf(mx0, __shfl_xor_sync(0xffffffffu, mx0, 1));
        mx0 = fmaxf(mx0, __shfl_xor_sync(0xffffffffu, mx0, 2));
        mx1 = fmaxf(mx1, __shfl_xor_sync(0xffffffffu, mx1, 1));
        mx1 = fmaxf(mx1, __shfl_xor_sync(0xffffffffu, mx1, 2));
        float mn0 = fmaxf(mrow0, mx0), mn1 = fmaxf(mrow1, mx1);
        float a0 = __expf(mrow0 - mn0), a1 = __expf(mrow1 - mn1);
        float sum0 = 0.f, sum1 = 0.f;
        #pragma unroll
        for (int nt = 0; nt < 8; nt++) {
            s[nt][0] = __expf(s[nt][0] - mn0); sum0 += s[nt][0];
            s[nt][1] = __expf(s[nt][1] - mn0); sum0 += s[nt][1];
            s[nt][2] = __expf(s[nt][2] - mn1); sum1 += s[nt][2];
            s[nt][3] = __expf(s[nt][3] - mn1); sum1 += s[nt][3];
        }
        sum0 += __shfl_xor_sync(0xffffffffu, sum0, 1);
        sum0 += __shfl_xor_sync(0xffffffffu, sum0, 2);
        sum1 += __shfl_xor_sync(0xffffffffu, sum1, 1);
        sum1 += __shfl_xor_sync(0xffffffffu, sum1, 2);
        lrow0 = lrow0 * a0 + sum0;  lrow1 = lrow1 * a1 + sum1;
        mrow0 = mn0;                mrow1 = mn1;
        #pragma unroll
        for (int nt = 0; nt < 8; nt++) {
            oacc[nt][0] *= a0; oacc[nt][1] *= a0;
            oacc[nt][2] *= a1; oacc[nt][3] *= a1;
        }

        #pragma unroll
        for (int nt = 0; nt < 8; nt++) {
            Ps[mr+qr  ][nt*8+qc*2  ] = tf32r(s[nt][0]);
            Ps[mr+qr  ][nt*8+qc*2+1] = tf32r(s[nt][1]);
            Ps[mr+qr+8][nt*8+qc*2  ] = tf32r(s[nt][2]);
            Ps[mr+qr+8][nt*8+qc*2+1] = tf32r(s[nt][3]);
        }
        __syncwarp();
        #pragma unroll
        for (int ks = 0; ks < 8; ks++) {
            uint32_t af[4] = {
                __float_as_uint(Ps[mr+qr  ][ks*8+qc  ]),
                __float_as_uint(Ps[mr+qr+8][ks*8+qc  ]),
                __float_as_uint(Ps[mr+qr  ][ks*8+qc+4]),
                __float_as_uint(Ps[mr+qr+8][ks*8+qc+4]) };
            #pragma unroll
            for (int nt = 0; nt < 8; nt++) {
                uint32_t bb[2] = {
                    __float_as_uint(Vs[(ks*8+qc  )*VSTR + nt*8+qr]),
                    __float_as_uint(Vs[(ks*8+qc+4)*VSTR + nt*8+qr]) };
                mma_tf32(oacc[nt], af, bb);
            }
        }
        __syncthreads();
    }

    float inv0 = 1.f / lrow0, inv1 = 1.f / lrow1;
    #pragma unroll
    for (int nt = 0; nt < 8; nt++) {
        int col = nt * 8 + qc * 2;
        *(float2*)(Op + (long)(mr+qr  ) * EMBED + col) =
            make_float2(tf32r(oacc[nt][0] * inv0), tf32r(oacc[nt][1] * inv0));
        *(float2*)(Op + (long)(mr+qr+8) * EMBED + col) =
            make_float2(tf32r(oacc[nt][2] * inv1), tf32r(oacc[nt][3] * inv1));
    }
}

// ---------------- LayerNorm(512) + exact GELU, in place (tf32 out) ----------
__global__ void ln_gelu_kernel(float* __restrict__ y,
                               const float* __restrict__ sc,
                               const float* __restrict__ bi)
{
    float* row = y + (long)blockIdx.x * (2 * EMBED);
    int t = threadIdx.x;
    float a = row[t], b = row[t + 256];

    __shared__ float red[256];
    red[t] = a + b; __syncthreads();
    for (int s = 128; s > 0; s >>= 1) {
        if (t < s) red[t] += red[t + s];
        __syncthreads();
    }
    float mean = red[0] * (1.f / 512.f);
    __syncthreads();

    float da = a - mean, db = b - mean;
    red[t] = da * da + db * db; __syncthreads();
    for (int s = 128; s > 0; s >>= 1) {
        if (t < s) red[t] += red[t + s];
        __syncthreads();
    }
    float inv = rsqrtf(red[0] * (1.f / 512.f) + 1e-5f);

    float g1 = da * inv * sc[t]       + bi[t];
    float g2 = db * inv * sc[t + 256] + bi[t + 256];
    row[t]       = tf32r(0.5f * g1 * (1.f + erff(g1 * 0.70710678118654752f)));
    row[t + 256] = tf32r(0.5f * g2 * (1.f + erff(g2 * 0.70710678118654752f)));
}

// ---------------- host side --------------------------------------------------
extern "C" void kernel_launch(void* const* d_in, const int* in_sizes, int n_in,
                              void* d_out, int out_size)
{
    const float* x0       = (const float*)d_in[0];
    const float* x1       = (const float*)d_in[1];
    const float* Wqk      = (const float*)d_in[2];
    const float* bqk      = (const float*)d_in[3];
    const float* Wv       = (const float*)d_in[4];
    const float* bv       = (const float*)d_in[5];
    const float* Wout     = (const float*)d_in[6];
    const float* bout     = (const float*)d_in[7];
    const float* W0       = (const float*)d_in[8];
    const float* b0       = (const float*)d_in[9];
    const float* ln_scale = (const float*)d_in[10];
    const float* ln_bias  = (const float*)d_in[11];
    const float* W3       = (const float*)d_in[12];
    const float* b3       = (const float*)d_in[13];
    float* out = (float*)d_out;

    float *xr, *w, *Bst, *bf, *qkv, *m, *y;
    cudaGetSymbolAddress((void**)&xr,  g_xr);
    cudaGetSymbolAddress((void**)&w,   g_w);
    cudaGetSymbolAddress((void**)&Bst, g_Bst);
    cudaGetSymbolAddress((void**)&bf,  g_bf);
    cudaGetSymbolAddress((void**)&qkv, g_qkv);
    cudaGetSymbolAddress((void**)&m,   g_m);
    cudaGetSymbolAddress((void**)&y,   g_y);

    cudaFuncSetAttribute(flash_kernel,
                         cudaFuncAttributeMaxDynamicSharedMemorySize, FL_SMEM);

    // 0) tf32-round activations + weights into scratch
    CopyJobs jobs;
    jobs.src[0] = x0;              jobs.dst[0] = xr;            jobs.n[0] = SZ;
    jobs.src[1] = x1;              jobs.dst[1] = xr + SZ;       jobs.n[1] = SZ;
    jobs.src[2] = Wqk;             jobs.dst[2] = w + WQK_R;     jobs.n[2] = 65536;
    jobs.src[3] = Wv;              jobs.dst[3] = w + WV_R;      jobs.n[3] = 65536;
    jobs.src[4] = Wout;            jobs.dst[4] = w + WOUT_R;    jobs.n[4] = 65536;
    jobs.src[5] = W0 + 256*512;    jobs.dst[5] = w + W0BOT_R;   jobs.n[5] = 131072;
    jobs.src[6] = W0;              jobs.dst[6] = Bst;           jobs.n[6] = 131072;
    jobs.src[7] = W3;              jobs.dst[7] = w + W3_R;      jobs.n[7] = 131072;
    tf32_copy_multi<<<dim3(64, NJOBS, 1), 256>>>(jobs);

    // 0b) Wfused = Wout_r @ W0bot_r -> Bstack rows 256..511 ; fused bias
    mma_gemm<0,1><<<dim3(4, 2, 1), 256>>>(
        w + WOUT_R, nullptr, nullptr, 0, w + W0BOT_R, nullptr,
        nullptr, nullptr, nullptr, nullptr,
        Bst + 256*512, 0, 256, 512, 256, 256, 512, 512, 0);
    bias_fuse_kernel<<<2, 256>>>(bout, W0 + 256*512, b0, bf);

    // 1) projections: z {0:x0@Wqk, 1:x1@Wqk, 2:x0@Wv, 3:x1@Wv} -> g_qkv[z]
    mma_gemm<0,1><<<dim3(2, 64, 4), 256>>>(
        xr, xr + SZ, nullptr, 0, w + WQK_R, w + WV_R, bqk, bv, nullptr, nullptr,
        qkv, SZ, ROWS, EMBED, EMBED, EMBED, EMBED, EMBED, 0);

    // 2) flash cross-attention, both directions
    flash_kernel<<<dim3(SEQ/64, BH, 2), 128, FL_SMEM>>>(qkv, m);

    // 3) y_z = x_z @ W0top + m_z @ Wfused + bfused   (split-A, stacked B)
    mma_gemm<1,0><<<dim3(4, 64, 2), 256>>>(
        xr, xr + SZ, m, SZ, Bst, Bst, bf, bf, nullptr, nullptr,
        y, (long)ROWS * 512, ROWS, 512, 512, EMBED, 512, 512, 0);

    // 4) LayerNorm + GELU in place (both streams), tf32 output
    ln_gelu_kernel<<<2 * ROWS, 256>>>(y, ln_scale, ln_bias);

    // 5) out_z = x_z + y_z @ W3 + b3
    mma_gemm<0,0><<<dim3(2, 64, 2), 256>>>(
        y, y + (long)ROWS * 512, nullptr, 0, w + W3_R, w + W3_R, b3, b3, x0, x1,
        out, SZ, ROWS, EMBED, 512, 512, EMBED, EMBED, EMBED);
}